// round 15
// baseline (speedup 1.0000x reference)
#include <cuda_runtime.h>
#include <cuda_fp16.h>
#include <string.h>

#define NN 50000
#define NE 800000
#define EP (NE + NN)        // edges + self loops
#define C  64
#define H  4
#define HC 256              // H * C
#define NEG_SLOPE 0.2f
#define BN_EPS 1e-5f

#define SCAN_BLK 1024
#define NSCAN ((NN + SCAN_BLK - 1) / SCAN_BLK)   // 49
#define GEMM_BLOCKS ((NN + 63) / 64)             // 782
#define CNT_BLOCKS ((EP + 255) / 256)            // 3321

// ---------------- scratch (static device globals; no runtime alloc) ----------
__device__ uint2  g_xh2[NN * 64];         // xh fp16: [NN][64] uint2=4 halves (25.6 MB)
__device__ float4 g_alsrc4[NN];           // per-node src logits, 4 heads
__device__ float4 g_aldst4[NN];           // per-node dst logits, 4 heads
__device__ float  g_tmp[NN * C];          // GAT output scratch (layer0 pre-BN)
__device__ int    g_cnt[NN];
__device__ int    g_cur[NN];
__device__ int    g_off[NN + 1];
__device__ int    g_csr[EP];
__device__ int    g_bsum[NSCAN];
__device__ int    g_scan_rdy;             // publish counter for fused scan
__device__ float  g_bnsum[2][128];        // per-layer BN raw sums [sum64|sumsq64]
__device__ int    g_is32;                 // 1 -> edge_index is int32, 0 -> int64
__device__ unsigned g_maxkey[4];          // encoded global max of alsrc per head

__device__ __forceinline__ float lrelu(float v) { return v > 0.f ? v : NEG_SLOPE * v; }

// order-preserving float <-> uint encoding for atomicMax
__device__ __forceinline__ unsigned fenc(float f) {
    unsigned u = __float_as_uint(f);
    return (u & 0x80000000u) ? ~u : (u | 0x80000000u);
}
__device__ __forceinline__ float fdec(unsigned k) {
    unsigned u = (k & 0x80000000u) ? (k & 0x7fffffffu) : ~k;
    return __uint_as_float(u);
}

__device__ __forceinline__ unsigned h2_to_u(__half2 h) {
    unsigned u; memcpy(&u, &h, 4); return u;
}
__device__ __forceinline__ __half2 u_to_h2(unsigned u) {
    __half2 h; memcpy(&h, &u, 4); return h;
}

// Safe edge-index read: dtype chosen at runtime, result clamped into [0, NN).
__device__ __forceinline__ int edge_val(const void* ei, int pos) {
    long long v = g_is32 ? (long long)((const int*)ei)[pos]
                         : ((const long long*)ei)[pos];
    int r = (int)v;
    if (r < 0) r = 0;
    if (r >= NN) r = NN - 1;
    return r;
}

// ---------------- init: zero counters + dtype detect + scan counter ----------
__global__ void k_init(const int* __restrict__ ei32) {
    if (blockIdx.x == 0 && threadIdx.x == 0) g_scan_rdy = 0;
    if (blockIdx.x < 196) {
        int i = blockIdx.x * 256 + threadIdx.x;
        if (i < NN) { g_cnt[i] = 0; g_cur[i] = 0; }
    } else {
        __shared__ int s_any;
        if (threadIdx.x == 0) s_any = 0;
        __syncthreads();
        for (int k = threadIdx.x; k < 4096; k += 256) {
            if (ei32[2 * k + 1] != 0) s_any = 1;   // benign race
        }
        __syncthreads();
        if (threadIdx.x == 0) g_is32 = s_any;
    }
}

// ---- fused exclusive scan of g_cnt -> g_off (single kernel, 49 blocks) ------
__global__ void k_scanf() {
    __shared__ int swarp[32];
    __shared__ int sexc[32];
    __shared__ int sbase;
    int t = threadIdx.x, lane = t & 31, wid = t >> 5;
    int i = blockIdx.x * SCAN_BLK + t;
    int v = (i < NN) ? g_cnt[i] : 0;
    int incl = v;
#pragma unroll
    for (int o = 1; o < 32; o <<= 1) {
        int u = __shfl_up_sync(0xffffffffu, incl, o);
        if (lane >= o) incl += u;
    }
    if (lane == 31) swarp[wid] = incl;
    __syncthreads();
    if (wid == 0) {
        int s = swarp[lane];
        int in2 = s;
#pragma unroll
        for (int o = 1; o < 32; o <<= 1) {
            int u = __shfl_up_sync(0xffffffffu, in2, o);
            if (lane >= o) in2 += u;
        }
        sexc[lane] = in2 - s;                 // exclusive warp base
        if (lane == 31) {                     // in2 == block total
            g_bsum[blockIdx.x] = in2;
            __threadfence();
            atomicAdd(&g_scan_rdy, 1);
            while (*(volatile int*)&g_scan_rdy < NSCAN) { }
            __threadfence();
            int base = 0, total = 0;
            for (int b = 0; b < NSCAN; b++) {
                int bv = g_bsum[b];
                if (b < (int)blockIdx.x) base += bv;
                total += bv;
            }
            sbase = base;
            if (blockIdx.x == 0) g_off[NN] = total;
        }
    }
    __syncthreads();
    if (i < NN) g_off[i] = (incl - v) + sexc[wid] + sbase;
}

__global__ void k_fill(const void* __restrict__ ei) {
    int e = blockIdx.x * blockDim.x + threadIdx.x;
    if (e >= EP) return;
    int src, dst;
    if (e < NE) { src = edge_val(ei, e); dst = edge_val(ei, NE + e); }
    else        { src = e - NE;          dst = e - NE; }
    int idx = g_off[dst] + atomicAdd(&g_cur[dst], 1);
    if (idx >= 0 && idx < EP) g_csr[idx] = src;
}

// ---------------- GEMM + logits + global max (+ optional fused edge count) ---
// Blocks [0, GEMM_BLOCKS): GEMM. Blocks [GEMM_BLOCKS, ...): edge counting
// (layer 0 only) — latency-bound work hidden under the FMA-bound GEMM.
// fuse_bn != 0 -> xin = g_tmp with layer-0 BN+ReLU (computed from raw sums).
__global__ void __launch_bounds__(256) k_gemm(const float* __restrict__ xin_ext,
                                              const float* __restrict__ W,
                                              const float* __restrict__ asrc,
                                              const float* __restrict__ adst,
                                              int fuse_bn,
                                              const float* __restrict__ gamma_prev,
                                              const float* __restrict__ beta_prev,
                                              const void* __restrict__ ei) {
    // ---- fused edge-count part (extra blocks, layer 0 only) -----------------
    if (blockIdx.x >= GEMM_BLOCKS) {
        int e = (blockIdx.x - GEMM_BLOCKS) * 256 + threadIdx.x;
        if (e < EP) {
            int dst = (e < NE) ? edge_val(ei, NE + e) : (e - NE);
            atomicAdd(&g_cnt[dst], 1);
        }
        return;
    }

    const float* xin = fuse_bn ? g_tmp : xin_ext;
    __shared__ float4 at4[64 * 17];          // A^T tile: [k][row], 68-float rows (pad)
    __shared__ float sa[256], sdv[256];
    __shared__ float ssc[64], ssh[64];
    __shared__ unsigned bm[4];
    float* at = (float*)at4;
    int t = threadIdx.x;
    int row0 = blockIdx.x * 64;
    int bank = fuse_bn ? 1 : 0;

    if (blockIdx.x == 0) {                    // reset accumulators for this layer
        if (t < 4) g_maxkey[t] = 0u;
        if (t < 128) g_bnsum[bank][t] = 0.f;  // this layer's BN sums (filled by k_agg)
    }
    sa[t] = asrc[t]; sdv[t] = adst[t];
    if (t < 4) bm[t] = 0u;
    if (fuse_bn && t < 64) {                  // scale/shift from prev layer's raw sums
        float mean = g_bnsum[0][t] * (1.f / NN);
        float var  = g_bnsum[0][64 + t] * (1.f / NN) - mean * mean;
        float sc = __ldg(&gamma_prev[t]) * rsqrtf(var + BN_EPS);
        ssc[t] = sc;
        ssh[t] = __ldg(&beta_prev[t]) - mean * sc;
    }
    __syncthreads();

    // load A tile transposed: at[k*68 + row] = xin[(row0+row)*64 + k]
#pragma unroll
    for (int j = 0; j < 16; j++) {
        int idx = t + j * 256;               // 0..4095
        int row = idx >> 6, k = idx & 63;
        int gr = row0 + row;
        float v = (gr < NN) ? xin[(size_t)gr * 64 + k] : 0.f;
        if (fuse_bn) v = fmaxf(fmaf(ssc[k], v, ssh[k]), 0.f);
        at[k * 68 + row] = v;
    }
    __syncthreads();

    int lane = t & 31;
    int rbase = (t >> 5) * 8;                // 0,8,...,56
    int cbase = lane * 8;                    // 0,8,...,248
    int head  = lane >> 3;                   // cols cbase..cbase+7 all in this head
    const float4* Wv = (const float4*)W;

    float acc[8][8];
#pragma unroll
    for (int r = 0; r < 8; r++)
#pragma unroll
        for (int c = 0; c < 8; c++) acc[r][c] = 0.f;

    for (int k = 0; k < 64; k++) {
        float4 a0 = at4[k * 17 + (rbase >> 2)];
        float4 a1 = at4[k * 17 + (rbase >> 2) + 1];
        float4 w0 = __ldg(&Wv[(k * HC + cbase) >> 2]);
        float4 w1 = __ldg(&Wv[((k * HC + cbase) >> 2) + 1]);
        float a[8] = {a0.x, a0.y, a0.z, a0.w, a1.x, a1.y, a1.z, a1.w};
        float w[8] = {w0.x, w0.y, w0.z, w0.w, w1.x, w1.y, w1.z, w1.w};
#pragma unroll
        for (int r = 0; r < 8; r++)
#pragma unroll
            for (int c = 0; c < 8; c++) acc[r][c] = fmaf(a[r], w[c], acc[r][c]);
    }

    // ---- per-row, per-head logits via intra-group (8-lane) reduction --------
#pragma unroll
    for (int r = 0; r < 8; r++) {
        int row = row0 + rbase + r;
        float ps = 0.f, pd = 0.f;
#pragma unroll
        for (int c = 0; c < 8; c++) {
            ps = fmaf(acc[r][c], sa[cbase + c], ps);
            pd = fmaf(acc[r][c], sdv[cbase + c], pd);
        }
#pragma unroll
        for (int o = 1; o < 8; o <<= 1) {
            ps += __shfl_xor_sync(0xffffffffu, ps, o);
            pd += __shfl_xor_sync(0xffffffffu, pd, o);
        }
        if ((lane & 7) == 0 && row < NN) {
            ((float*)&g_alsrc4[row])[head] = ps;
            ((float*)&g_aldst4[row])[head] = pd;
            atomicMax(&bm[head], fenc(ps));
        }
    }

    // ---- fp16 xh write ------------------------------------------------------
#pragma unroll
    for (int r = 0; r < 8; r++) {
        int row = row0 + rbase + r;
        if (row < NN) {
            uint2 u0, u1;
            u0.x = h2_to_u(__floats2half2_rn(acc[r][0], acc[r][1]));
            u0.y = h2_to_u(__floats2half2_rn(acc[r][2], acc[r][3]));
            u1.x = h2_to_u(__floats2half2_rn(acc[r][4], acc[r][5]));
            u1.y = h2_to_u(__floats2half2_rn(acc[r][6], acc[r][7]));
            g_xh2[(size_t)row * 64 + (cbase >> 2)]     = u0;
            g_xh2[(size_t)row * 64 + (cbase >> 2) + 1] = u1;
        }
    }

    __syncthreads();
    if (t < 4) atomicMax(&g_maxkey[t], bm[t]);
}

// ---------------- fused softmax + aggregate + BN stats (warp per node) -------
// Batched edges (32/warp-iter) + unnormalized accumulate (softmax linearity).
// BN stats aggregated per-block in smem, then 128 global atomics per block.
__global__ void __launch_bounds__(256) k_agg(const float* __restrict__ bias,
                                             float* __restrict__ out_ext,
                                             int bank) {
    float* out = out_ext ? out_ext : g_tmp;
    __shared__ float4 sm4[8][64];
    __shared__ float sp[8][4][32];           // per-warp p values [head][edge]
    __shared__ int   ssrc[8][32];            // per-warp src indices
    __shared__ float bsn[128];               // block BN partials [sum64|sumsq64]
    int warp = threadIdx.x >> 5, lane = threadIdx.x & 31;
    int t = threadIdx.x;
    if (t < 128) bsn[t] = 0.f;
    int n = blockIdx.x * 8 + warp;           // grid is exactly NN/8
    int beg = g_off[n], end = g_off[n + 1];
    float4 ad = g_aldst4[n];
    float m0 = fmaxf(fdec(g_maxkey[0]) + ad.x, 0.f);
    float m1 = fmaxf(fdec(g_maxkey[1]) + ad.y, 0.f);
    float m2 = fmaxf(fdec(g_maxkey[2]) + ad.z, 0.f);
    float m3 = fmaxf(fdec(g_maxkey[3]) + ad.w, 0.f);
    int hsel = lane >> 4;                    // 0 or 1

    float d0 = 0.f, d1 = 0.f, d2 = 0.f, d3 = 0.f;   // per-lane denom partials
    float4 acc0 = make_float4(0.f, 0.f, 0.f, 0.f);
    float4 acc1 = make_float4(0.f, 0.f, 0.f, 0.f);

    for (int base = beg; base < end; base += 32) {
        int cnt = end - base; if (cnt > 32) cnt = 32;
        // phase 1: 32 edges in parallel, one per lane (MLP=32)
        int idx = base + (lane < cnt ? lane : cnt - 1);
        int s_l = g_csr[idx];
        float4 as = g_alsrc4[s_l];
        float p0 = __expf(lrelu(as.x + ad.x) - m0);
        float p1 = __expf(lrelu(as.y + ad.y) - m1);
        float p2 = __expf(lrelu(as.z + ad.z) - m2);
        float p3 = __expf(lrelu(as.w + ad.w) - m3);
        if (lane >= cnt) { p0 = p1 = p2 = p3 = 0.f; }
        d0 += p0; d1 += p1; d2 += p2; d3 += p3;
        sp[warp][0][lane] = p0; sp[warp][1][lane] = p1;
        sp[warp][2][lane] = p2; sp[warp][3][lane] = p3;
        ssrc[warp][lane] = s_l;
        __syncwarp();
        // phase 2: gather — independent iterations, deep MLP
#pragma unroll 4
        for (int e = 0; e < cnt; e++) {
            int s = ssrc[warp][e];                   // LDS broadcast
            float pA = sp[warp][hsel][e];
            float pB = sp[warp][2 + hsel][e];
            const uint2* xr = &g_xh2[(size_t)s * 64];
            uint2 u0 = xr[lane];
            uint2 u1 = xr[32 + lane];
            float2 f00 = __half22float2(u_to_h2(u0.x));
            float2 f01 = __half22float2(u_to_h2(u0.y));
            float2 f10 = __half22float2(u_to_h2(u1.x));
            float2 f11 = __half22float2(u_to_h2(u1.y));
            acc0.x = fmaf(pA, f00.x, acc0.x); acc0.y = fmaf(pA, f00.y, acc0.y);
            acc0.z = fmaf(pA, f01.x, acc0.z); acc0.w = fmaf(pA, f01.y, acc0.w);
            acc1.x = fmaf(pB, f10.x, acc1.x); acc1.y = fmaf(pB, f10.y, acc1.y);
            acc1.z = fmaf(pB, f11.x, acc1.z); acc1.w = fmaf(pB, f11.y, acc1.w);
        }
        __syncwarp();
    }

    // warp-reduce the denominators
#pragma unroll
    for (int o = 16; o; o >>= 1) {
        d0 += __shfl_xor_sync(0xffffffffu, d0, o);
        d1 += __shfl_xor_sync(0xffffffffu, d1, o);
        d2 += __shfl_xor_sync(0xffffffffu, d2, o);
        d3 += __shfl_xor_sync(0xffffffffu, d3, o);
    }
    float ivA = 1.f / ((hsel ? d1 : d0) + 1e-16f);
    float ivB = 1.f / ((hsel ? d3 : d2) + 1e-16f);
    acc0.x *= ivA; acc0.y *= ivA; acc0.z *= ivA; acc0.w *= ivA;
    acc1.x *= ivB; acc1.y *= ivB; acc1.z *= ivB; acc1.w *= ivB;

    sm4[warp][lane]      = acc0;
    sm4[warp][32 + lane] = acc1;
    __syncthreads();                          // also covers bsn zeroing
    const float* smf = (const float*)sm4[warp];
#pragma unroll
    for (int j = 0; j < 2; j++) {
        int c = lane + 32 * j;
        float v = (smf[c] + smf[c + 64] + smf[c + 128] + smf[c + 192]) * 0.25f
                  + __ldg(&bias[c]);
        out[(size_t)n * C + c] = v;
        atomicAdd(&bsn[c], v);               // smem aggregation (fast)
        atomicAdd(&bsn[64 + c], v * v);
    }
    __syncthreads();
    if (t < 128) atomicAdd(&g_bnsum[bank][t], bsn[t]);  // 128 global atomics/block
}

// ---------------- BN apply (scale/shift computed inline from raw sums) -------
__global__ void k_bn_apply(const float* __restrict__ in,
                           float* __restrict__ out,
                           const float* __restrict__ gamma,
                           const float* __restrict__ beta) {
    __shared__ float ssc[64], ssh[64];
    int t = threadIdx.x;
    if (t < 64) {
        float mean = g_bnsum[1][t] * (1.f / NN);
        float var  = g_bnsum[1][64 + t] * (1.f / NN) - mean * mean;
        float sc = __ldg(&gamma[t]) * rsqrtf(var + BN_EPS);
        ssc[t] = sc;
        ssh[t] = __ldg(&beta[t]) - mean * sc;
    }
    __syncthreads();
    int i = blockIdx.x * 256 + t;
    if (i >= NN * C) return;
    int c = i & 63;
    out[i] = fmaxf(fmaf(ssc[c], in[i], ssh[c]), 0.f);
}

// ---------------- launch -----------------------------------------------------
extern "C" void kernel_launch(void* const* d_in, const int* in_sizes, int n_in,
                              void* d_out, int out_size) {
    const float* x  = (const float*)d_in[0];
    const void*  ei = d_in[1];                 // int32 or int64, detected on device
    float* out = (float*)d_out;

    const float* W[2]     = {(const float*)d_in[3],  (const float*)d_in[9]};
    const float* asrc[2]  = {(const float*)d_in[4],  (const float*)d_in[10]};
    const float* adst[2]  = {(const float*)d_in[5],  (const float*)d_in[11]};
    const float* bias[2]  = {(const float*)d_in[6],  (const float*)d_in[12]};
    const float* gamma[2] = {(const float*)d_in[7],  (const float*)d_in[13]};
    const float* beta[2]  = {(const float*)d_in[8],  (const float*)d_in[14]};

    bool both_outputs = (out_size >= 2 * NN * C);
    float* saved_ptr = both_outputs ? (out + (size_t)NN * C) : nullptr; // nullptr -> g_tmp

    // init (counters + dtype) --------------------------------------------------
    k_init<<<197, 256>>>((const int*)ei);

    // layer-0 GEMM with edge-count blocks fused (count hides under GEMM) ------
    k_gemm<<<GEMM_BLOCKS + CNT_BLOCKS, 256>>>(x, W[0], asrc[0], adst[0], 0,
                                              nullptr, nullptr, ei);
    k_scanf<<<NSCAN, SCAN_BLK>>>();
    k_fill<<<CNT_BLOCKS, 256>>>(ei);

    // layer 0 aggregate (writes g_tmp + BN sums bank 0)
    k_agg<<<NN / 8, 256>>>(bias[0], nullptr, 0);

    // layer 1: BN0+ReLU fused into GEMM load (scale/shift from raw sums)
    k_gemm<<<GEMM_BLOCKS, 256>>>(nullptr, W[1], asrc[1], adst[1], 1,
                                 gamma[0], beta[0], nullptr);
    k_agg<<<NN / 8, 256>>>(bias[1], saved_ptr, 1);

    // BN1 apply (scale/shift from raw sums bank 1)
    k_bn_apply<<<(NN * C + 255) / 256, 256>>>(saved_ptr, out, gamma[1], beta[1]);
}

// round 16
// speedup vs baseline: 1.0316x; 1.0316x over previous
#include <cuda_runtime.h>
#include <cuda_fp16.h>
#include <string.h>

#define NN 50000
#define NE 800000
#define EP (NE + NN)        // edges + self loops
#define C  64
#define H  4
#define HC 256              // H * C
#define NEG_SLOPE 0.2f
#define BN_EPS 1e-5f

#define GEMM_BLOCKS ((NN + 63) / 64)             // 782
#define CNT_BLOCKS ((EP + 255) / 256)            // 3321
#define SF_BLOCKS 148                            // persistent scan+fill blocks
#define SF_THREADS (SF_BLOCKS * 1024)            // 151552 >= NN

// ---------------- scratch (static device globals; no runtime alloc) ----------
__device__ uint2  g_xh2[NN * 64];         // xh fp16: [NN][64] uint2=4 halves (25.6 MB)
__device__ float4 g_alsrc4[NN];           // per-node src logits, 4 heads
__device__ float4 g_aldst4[NN];           // per-node dst logits, 4 heads
__device__ float  g_tmp[NN * C];          // GAT output scratch (layer0 pre-BN)
__device__ int    g_cnt[NN];
__device__ int    g_cur[NN];
__device__ int    g_off[NN + 1];
__device__ int    g_csr[EP];
__device__ int    g_bsum[SF_BLOCKS];
__device__ int    g_scan_rdy;             // grid barrier counter (0 ->148 ->296)
__device__ float  g_bnsum[2][128];        // per-layer BN raw sums [sum64|sumsq64]
__device__ int    g_is32;                 // 1 -> edge_index is int32, 0 -> int64
__device__ unsigned g_maxkey[4];          // encoded global max of alsrc per head

__device__ __forceinline__ float lrelu(float v) { return v > 0.f ? v : NEG_SLOPE * v; }

// order-preserving float <-> uint encoding for atomicMax
__device__ __forceinline__ unsigned fenc(float f) {
    unsigned u = __float_as_uint(f);
    return (u & 0x80000000u) ? ~u : (u | 0x80000000u);
}
__device__ __forceinline__ float fdec(unsigned k) {
    unsigned u = (k & 0x80000000u) ? (k & 0x7fffffffu) : ~k;
    return __uint_as_float(u);
}

__device__ __forceinline__ unsigned h2_to_u(__half2 h) {
    unsigned u; memcpy(&u, &h, 4); return u;
}
__device__ __forceinline__ __half2 u_to_h2(unsigned u) {
    __half2 h; memcpy(&h, &u, 4); return h;
}

// Safe edge-index read: dtype chosen at runtime, result clamped into [0, NN).
__device__ __forceinline__ int edge_val(const void* ei, int pos) {
    long long v = g_is32 ? (long long)((const int*)ei)[pos]
                         : ((const long long*)ei)[pos];
    int r = (int)v;
    if (r < 0) r = 0;
    if (r >= NN) r = NN - 1;
    return r;
}

// ---------------- init: zero counters + dtype detect + barrier counter -------
__global__ void k_init(const int* __restrict__ ei32) {
    if (blockIdx.x == 0 && threadIdx.x == 0) g_scan_rdy = 0;
    if (blockIdx.x < 196) {
        int i = blockIdx.x * 256 + threadIdx.x;
        if (i < NN) { g_cnt[i] = 0; g_cur[i] = 0; }
    } else {
        __shared__ int s_any;
        if (threadIdx.x == 0) s_any = 0;
        __syncthreads();
        for (int k = threadIdx.x; k < 4096; k += 256) {
            if (ei32[2 * k + 1] != 0) s_any = 1;   // benign race
        }
        __syncthreads();
        if (threadIdx.x == 0) g_is32 = s_any;
    }
}

// ---- persistent scan + fill (148 co-resident blocks, 2 grid barriers) -------
__global__ void __launch_bounds__(1024) k_scanfill(const void* __restrict__ ei) {
    __shared__ int swarp[32];
    __shared__ int sexc[32];
    __shared__ int sbase;
    int t = threadIdx.x, lane = t & 31, wid = t >> 5;
    int gid = blockIdx.x * 1024 + t;

    // ---- phase A: block-local scan of g_cnt (blocks >= 49 are all-zero) -----
    int v = (gid < NN) ? g_cnt[gid] : 0;
    int incl = v;
#pragma unroll
    for (int o = 1; o < 32; o <<= 1) {
        int u = __shfl_up_sync(0xffffffffu, incl, o);
        if (lane >= o) incl += u;
    }
    if (lane == 31) swarp[wid] = incl;
    __syncthreads();
    if (wid == 0) {
        int s = swarp[lane];
        int in2 = s;
#pragma unroll
        for (int o = 1; o < 32; o <<= 1) {
            int u = __shfl_up_sync(0xffffffffu, in2, o);
            if (lane >= o) in2 += u;
        }
        sexc[lane] = in2 - s;                 // exclusive warp base
        if (lane == 31) {                     // in2 == block total
            g_bsum[blockIdx.x] = in2;
            __threadfence();
            atomicAdd(&g_scan_rdy, 1);
            while (*(volatile int*)&g_scan_rdy < SF_BLOCKS) { }
            __threadfence();
            int base = 0, total = 0;
            for (int b = 0; b < SF_BLOCKS; b++) {
                int bv = g_bsum[b];
                if (b < (int)blockIdx.x) base += bv;
                total += bv;
            }
            sbase = base;
            if (blockIdx.x == 0) g_off[NN] = total;
        }
    }
    __syncthreads();
    if (gid < NN) g_off[gid] = (incl - v) + sexc[wid] + sbase;

    // ---- grid barrier #2: all g_off writes visible ---------------------------
    __threadfence();
    __syncthreads();
    if (t == 0) {
        atomicAdd(&g_scan_rdy, 1);
        while (*(volatile int*)&g_scan_rdy < 2 * SF_BLOCKS) { }
    }
    __syncthreads();
    __threadfence();

    // ---- phase B: fill CSR (grid-stride over all edges) ----------------------
    for (int e = gid; e < EP; e += SF_THREADS) {
        int src, dst;
        if (e < NE) { src = edge_val(ei, e); dst = edge_val(ei, NE + e); }
        else        { src = e - NE;          dst = e - NE; }
        int idx = g_off[dst] + atomicAdd(&g_cur[dst], 1);
        if (idx >= 0 && idx < EP) g_csr[idx] = src;
    }
}

// ---------------- GEMM + logits + global max (+ optional fused edge count) ---
// Blocks [0, GEMM_BLOCKS): GEMM. Blocks [GEMM_BLOCKS, ...): edge counting
// (layer 0 only). fuse_bn != 0 -> xin = g_tmp with BN0+ReLU from raw sums.
__global__ void __launch_bounds__(256) k_gemm(const float* __restrict__ xin_ext,
                                              const float* __restrict__ W,
                                              const float* __restrict__ asrc,
                                              const float* __restrict__ adst,
                                              int fuse_bn,
                                              const float* __restrict__ gamma_prev,
                                              const float* __restrict__ beta_prev,
                                              const void* __restrict__ ei) {
    // ---- fused edge-count part (extra blocks, layer 0 only) -----------------
    if (blockIdx.x >= GEMM_BLOCKS) {
        int e = (blockIdx.x - GEMM_BLOCKS) * 256 + threadIdx.x;
        if (e < EP) {
            int dst = (e < NE) ? edge_val(ei, NE + e) : (e - NE);
            atomicAdd(&g_cnt[dst], 1);
        }
        return;
    }

    const float* xin = fuse_bn ? g_tmp : xin_ext;
    __shared__ float4 at4[64 * 17];          // A^T tile: [k][row], 68-float rows (pad)
    __shared__ float sa[256], sdv[256];
    __shared__ float ssc[64], ssh[64];
    __shared__ unsigned bm[4];
    float* at = (float*)at4;
    int t = threadIdx.x;
    int row0 = blockIdx.x * 64;
    int bank = fuse_bn ? 1 : 0;

    if (blockIdx.x == 0) {                    // reset accumulators for this layer
        if (t < 4) g_maxkey[t] = 0u;
        if (t < 128) g_bnsum[bank][t] = 0.f;  // this layer's BN sums (filled by k_agg)
    }
    sa[t] = asrc[t]; sdv[t] = adst[t];
    if (t < 4) bm[t] = 0u;
    if (fuse_bn && t < 64) {                  // scale/shift from prev layer's raw sums
        float mean = g_bnsum[0][t] * (1.f / NN);
        float var  = g_bnsum[0][64 + t] * (1.f / NN) - mean * mean;
        float sc = __ldg(&gamma_prev[t]) * rsqrtf(var + BN_EPS);
        ssc[t] = sc;
        ssh[t] = __ldg(&beta_prev[t]) - mean * sc;
    }
    __syncthreads();

    // load A tile transposed: at[k*68 + row] = xin[(row0+row)*64 + k]
#pragma unroll
    for (int j = 0; j < 16; j++) {
        int idx = t + j * 256;               // 0..4095
        int row = idx >> 6, k = idx & 63;
        int gr = row0 + row;
        float v = (gr < NN) ? xin[(size_t)gr * 64 + k] : 0.f;
        if (fuse_bn) v = fmaxf(fmaf(ssc[k], v, ssh[k]), 0.f);
        at[k * 68 + row] = v;
    }
    __syncthreads();

    int lane = t & 31;
    int rbase = (t >> 5) * 8;                // 0,8,...,56
    int cbase = lane * 8;                    // 0,8,...,248
    int head  = lane >> 3;                   // cols cbase..cbase+7 all in this head
    const float4* Wv = (const float4*)W;

    float acc[8][8];
#pragma unroll
    for (int r = 0; r < 8; r++)
#pragma unroll
        for (int c = 0; c < 8; c++) acc[r][c] = 0.f;

    for (int k = 0; k < 64; k++) {
        float4 a0 = at4[k * 17 + (rbase >> 2)];
        float4 a1 = at4[k * 17 + (rbase >> 2) + 1];
        float4 w0 = __ldg(&Wv[(k * HC + cbase) >> 2]);
        float4 w1 = __ldg(&Wv[((k * HC + cbase) >> 2) + 1]);
        float a[8] = {a0.x, a0.y, a0.z, a0.w, a1.x, a1.y, a1.z, a1.w};
        float w[8] = {w0.x, w0.y, w0.z, w0.w, w1.x, w1.y, w1.z, w1.w};
#pragma unroll
        for (int r = 0; r < 8; r++)
#pragma unroll
            for (int c = 0; c < 8; c++) acc[r][c] = fmaf(a[r], w[c], acc[r][c]);
    }

    // ---- per-row, per-head logits via intra-group (8-lane) reduction --------
#pragma unroll
    for (int r = 0; r < 8; r++) {
        int row = row0 + rbase + r;
        float ps = 0.f, pd = 0.f;
#pragma unroll
        for (int c = 0; c < 8; c++) {
            ps = fmaf(acc[r][c], sa[cbase + c], ps);
            pd = fmaf(acc[r][c], sdv[cbase + c], pd);
        }
#pragma unroll
        for (int o = 1; o < 8; o <<= 1) {
            ps += __shfl_xor_sync(0xffffffffu, ps, o);
            pd += __shfl_xor_sync(0xffffffffu, pd, o);
        }
        if ((lane & 7) == 0 && row < NN) {
            ((float*)&g_alsrc4[row])[head] = ps;
            ((float*)&g_aldst4[row])[head] = pd;
            atomicMax(&bm[head], fenc(ps));
        }
    }

    // ---- fp16 xh write ------------------------------------------------------
#pragma unroll
    for (int r = 0; r < 8; r++) {
        int row = row0 + rbase + r;
        if (row < NN) {
            uint2 u0, u1;
            u0.x = h2_to_u(__floats2half2_rn(acc[r][0], acc[r][1]));
            u0.y = h2_to_u(__floats2half2_rn(acc[r][2], acc[r][3]));
            u1.x = h2_to_u(__floats2half2_rn(acc[r][4], acc[r][5]));
            u1.y = h2_to_u(__floats2half2_rn(acc[r][6], acc[r][7]));
            g_xh2[(size_t)row * 64 + (cbase >> 2)]     = u0;
            g_xh2[(size_t)row * 64 + (cbase >> 2) + 1] = u1;
        }
    }

    __syncthreads();
    if (t < 4) atomicMax(&g_maxkey[t], bm[t]);
}

// ---------------- fused softmax + aggregate + BN stats (warp per node) -------
__global__ void __launch_bounds__(256) k_agg(const float* __restrict__ bias,
                                             float* __restrict__ out_ext,
                                             int bank) {
    float* out = out_ext ? out_ext : g_tmp;
    __shared__ float4 sm4[8][64];
    __shared__ float sp[8][4][32];           // per-warp p values [head][edge]
    __shared__ int   ssrc[8][32];            // per-warp src indices
    __shared__ float bsn[128];               // block BN partials [sum64|sumsq64]
    int warp = threadIdx.x >> 5, lane = threadIdx.x & 31;
    int t = threadIdx.x;
    if (t < 128) bsn[t] = 0.f;
    int n = blockIdx.x * 8 + warp;           // grid is exactly NN/8
    int beg = g_off[n], end = g_off[n + 1];
    float4 ad = g_aldst4[n];
    float m0 = fmaxf(fdec(g_maxkey[0]) + ad.x, 0.f);
    float m1 = fmaxf(fdec(g_maxkey[1]) + ad.y, 0.f);
    float m2 = fmaxf(fdec(g_maxkey[2]) + ad.z, 0.f);
    float m3 = fmaxf(fdec(g_maxkey[3]) + ad.w, 0.f);
    int hsel = lane >> 4;                    // 0 or 1

    float d0 = 0.f, d1 = 0.f, d2 = 0.f, d3 = 0.f;   // per-lane denom partials
    float4 acc0 = make_float4(0.f, 0.f, 0.f, 0.f);
    float4 acc1 = make_float4(0.f, 0.f, 0.f, 0.f);

    for (int base = beg; base < end; base += 32) {
        int cnt = end - base; if (cnt > 32) cnt = 32;
        // phase 1: 32 edges in parallel, one per lane (MLP=32)
        int idx = base + (lane < cnt ? lane : cnt - 1);
        int s_l = g_csr[idx];
        float4 as = g_alsrc4[s_l];
        float p0 = __expf(lrelu(as.x + ad.x) - m0);
        float p1 = __expf(lrelu(as.y + ad.y) - m1);
        float p2 = __expf(lrelu(as.z + ad.z) - m2);
        float p3 = __expf(lrelu(as.w + ad.w) - m3);
        if (lane >= cnt) { p0 = p1 = p2 = p3 = 0.f; }
        d0 += p0; d1 += p1; d2 += p2; d3 += p3;
        sp[warp][0][lane] = p0; sp[warp][1][lane] = p1;
        sp[warp][2][lane] = p2; sp[warp][3][lane] = p3;
        ssrc[warp][lane] = s_l;
        __syncwarp();
        // phase 2: gather — independent iterations, deep MLP
#pragma unroll 4
        for (int e = 0; e < cnt; e++) {
            int s = ssrc[warp][e];                   // LDS broadcast
            float pA = sp[warp][hsel][e];
            float pB = sp[warp][2 + hsel][e];
            const uint2* xr = &g_xh2[(size_t)s * 64];
            uint2 u0 = xr[lane];
            uint2 u1 = xr[32 + lane];
            float2 f00 = __half22float2(u_to_h2(u0.x));
            float2 f01 = __half22float2(u_to_h2(u0.y));
            float2 f10 = __half22float2(u_to_h2(u1.x));
            float2 f11 = __half22float2(u_to_h2(u1.y));
            acc0.x = fmaf(pA, f00.x, acc0.x); acc0.y = fmaf(pA, f00.y, acc0.y);
            acc0.z = fmaf(pA, f01.x, acc0.z); acc0.w = fmaf(pA, f01.y, acc0.w);
            acc1.x = fmaf(pB, f10.x, acc1.x); acc1.y = fmaf(pB, f10.y, acc1.y);
            acc1.z = fmaf(pB, f11.x, acc1.z); acc1.w = fmaf(pB, f11.y, acc1.w);
        }
        __syncwarp();
    }

    // warp-reduce the denominators
#pragma unroll
    for (int o = 16; o; o >>= 1) {
        d0 += __shfl_xor_sync(0xffffffffu, d0, o);
        d1 += __shfl_xor_sync(0xffffffffu, d1, o);
        d2 += __shfl_xor_sync(0xffffffffu, d2, o);
        d3 += __shfl_xor_sync(0xffffffffu, d3, o);
    }
    float ivA = 1.f / ((hsel ? d1 : d0) + 1e-16f);
    float ivB = 1.f / ((hsel ? d3 : d2) + 1e-16f);
    acc0.x *= ivA; acc0.y *= ivA; acc0.z *= ivA; acc0.w *= ivA;
    acc1.x *= ivB; acc1.y *= ivB; acc1.z *= ivB; acc1.w *= ivB;

    sm4[warp][lane]      = acc0;
    sm4[warp][32 + lane] = acc1;
    __syncthreads();                          // also covers bsn zeroing
    const float* smf = (const float*)sm4[warp];
#pragma unroll
    for (int j = 0; j < 2; j++) {
        int c = lane + 32 * j;
        float v = (smf[c] + smf[c + 64] + smf[c + 128] + smf[c + 192]) * 0.25f
                  + __ldg(&bias[c]);
        out[(size_t)n * C + c] = v;
        atomicAdd(&bsn[c], v);               // smem aggregation (fast)
        atomicAdd(&bsn[64 + c], v * v);
    }
    __syncthreads();
    if (t < 128) atomicAdd(&g_bnsum[bank][t], bsn[t]);  // 128 global atomics/block
}

// ---------------- BN apply (scale/shift computed inline from raw sums) -------
__global__ void k_bn_apply(const float* __restrict__ in,
                           float* __restrict__ out,
                           const float* __restrict__ gamma,
                           const float* __restrict__ beta) {
    __shared__ float ssc[64], ssh[64];
    int t = threadIdx.x;
    if (t < 64) {
        float mean = g_bnsum[1][t] * (1.f / NN);
        float var  = g_bnsum[1][64 + t] * (1.f / NN) - mean * mean;
        float sc = __ldg(&gamma[t]) * rsqrtf(var + BN_EPS);
        ssc[t] = sc;
        ssh[t] = __ldg(&beta[t]) - mean * sc;
    }
    __syncthreads();
    int i = blockIdx.x * 256 + t;
    if (i >= NN * C) return;
    int c = i & 63;
    out[i] = fmaxf(fmaf(ssc[c], in[i], ssh[c]), 0.f);
}

// ---------------- launch -----------------------------------------------------
extern "C" void kernel_launch(void* const* d_in, const int* in_sizes, int n_in,
                              void* d_out, int out_size) {
    const float* x  = (const float*)d_in[0];
    const void*  ei = d_in[1];                 // int32 or int64, detected on device
    float* out = (float*)d_out;

    const float* W[2]     = {(const float*)d_in[3],  (const float*)d_in[9]};
    const float* asrc[2]  = {(const float*)d_in[4],  (const float*)d_in[10]};
    const float* adst[2]  = {(const float*)d_in[5],  (const float*)d_in[11]};
    const float* bias[2]  = {(const float*)d_in[6],  (const float*)d_in[12]};
    const float* gamma[2] = {(const float*)d_in[7],  (const float*)d_in[13]};
    const float* beta[2]  = {(const float*)d_in[8],  (const float*)d_in[14]};

    bool both_outputs = (out_size >= 2 * NN * C);
    float* saved_ptr = both_outputs ? (out + (size_t)NN * C) : nullptr; // nullptr -> g_tmp

    // init (counters + dtype + barrier counter)
    k_init<<<197, 256>>>((const int*)ei);

    // layer-0 GEMM with edge-count blocks fused
    k_gemm<<<GEMM_BLOCKS + CNT_BLOCKS, 256>>>(x, W[0], asrc[0], adst[0], 0,
                                              nullptr, nullptr, ei);
    // persistent scan + fill (one kernel, 2 grid barriers)
    k_scanfill<<<SF_BLOCKS, 1024>>>(ei);

    // layer 0 aggregate (writes g_tmp + BN sums bank 0)  [ncu capture slot]
    k_agg<<<NN / 8, 256>>>(bias[0], nullptr, 0);

    // layer 1: BN0+ReLU fused into GEMM load
    k_gemm<<<GEMM_BLOCKS, 256>>>(nullptr, W[1], asrc[1], adst[1], 1,
                                 gamma[0], beta[0], nullptr);
    k_agg<<<NN / 8, 256>>>(bias[1], saved_ptr, 1);

    // BN1 apply
    k_bn_apply<<<(NN * C + 255) / 256, 256>>>(saved_ptr, out, gamma[1], beta[1]);
}